// round 5
// baseline (speedup 1.0000x reference)
#include <cuda_runtime.h>
#include <cstdint>

// Problem constants (fixed shapes for this problem instance)
#define NMAX   100000
#define HID    16
#define MSG    16
#define TTYPES 8
#define NGATE  48   // 3*HID
#define COUT   32

// Padded SMEM row stride for the edge-type table: 260 floats (1040B).
// Bank offset of type t = (260*t) mod 32 = 4t  -> 8 types land on 8 distinct
// 4-bank groups, so a warp reading the same element index across mixed types
// is bank-conflict-free (and same-type lanes broadcast).
#define ROWPAD 260

// Scratch accumulator for segment-sum (m = scatter_add(msg, dst)). 6.4 MB.
// __device__ global: no allocation inside kernel_launch (harness rule).
__device__ __align__(16) float g_m[NMAX * MSG];

// ---------------------------------------------------------------------------
// Kernel 0: zero the accumulator (must run every launch; graph replays).
// ---------------------------------------------------------------------------
__global__ void zero_m_kernel(int n4) {
    int i = blockIdx.x * blockDim.x + threadIdx.x;
    if (i < n4) {
        reinterpret_cast<float4*>(g_m)[i] = make_float4(0.f, 0.f, 0.f, 0.f);
    }
}

// ---------------------------------------------------------------------------
// Kernel 1: per-edge message + scatter-add.
// msg[e][m] = sum_h A[etype[e]][m][h] * features[src[e]][h]
// g_m[dst[e]][:] += msg[e][:]
// ---------------------------------------------------------------------------
__global__ void __launch_bounds__(256) edge_kernel(
    const float* __restrict__ features,
    const int*   __restrict__ src,
    const int*   __restrict__ dst,
    const int*   __restrict__ etype,
    const float* __restrict__ edge_table,
    int E)
{
    __shared__ float sA[TTYPES * ROWPAD];

    // Cooperative load of the 8 x 256-float edge-type matrices (padded rows).
    for (int i = threadIdx.x; i < TTYPES * MSG * HID; i += blockDim.x) {
        int t = i >> 8;         // / 256
        int k = i & 255;        // % 256
        sA[t * ROWPAD + k] = edge_table[i];
    }
    __syncthreads();

    int e = blockIdx.x * blockDim.x + threadIdx.x;
    if (e >= E) return;

    int s = src[e];
    int d = dst[e];
    int t = etype[e];

    // Gather source features (64B, L2-resident: features table is 6.4 MB)
    const float4* hp = reinterpret_cast<const float4*>(features + (size_t)s * HID);
    float4 h0 = hp[0], h1 = hp[1], h2 = hp[2], h3 = hp[3];

    const float* A = sA + t * ROWPAD;

    float msg[MSG];
#pragma unroll
    for (int r = 0; r < MSG; r++) {
        const float4* ar = reinterpret_cast<const float4*>(A + r * HID);
        float4 a0 = ar[0], a1 = ar[1], a2 = ar[2], a3 = ar[3];
        float acc;
        acc  = a0.x * h0.x;           acc = fmaf(a0.y, h0.y, acc);
        acc  = fmaf(a0.z, h0.z, acc); acc = fmaf(a0.w, h0.w, acc);
        acc  = fmaf(a1.x, h1.x, acc); acc = fmaf(a1.y, h1.y, acc);
        acc  = fmaf(a1.z, h1.z, acc); acc = fmaf(a1.w, h1.w, acc);
        acc  = fmaf(a2.x, h2.x, acc); acc = fmaf(a2.y, h2.y, acc);
        acc  = fmaf(a2.z, h2.z, acc); acc = fmaf(a2.w, h2.w, acc);
        acc  = fmaf(a3.x, h3.x, acc); acc = fmaf(a3.y, h3.y, acc);
        acc  = fmaf(a3.z, h3.z, acc); acc = fmaf(a3.w, h3.w, acc);
        msg[r] = acc;
    }

    // Vectorized reductions: 4 x red.global.add.v4.f32 (sm_90+),
    // 4x fewer L2-atomic lane-ops than scalar atomicAdd.
    // g_m is 16B-aligned and d*MSG*4 = d*64 bytes, so each target is 16B-aligned.
    float* mp = g_m + (size_t)d * MSG;
#pragma unroll
    for (int i = 0; i < 4; i++) {
        asm volatile(
            "red.global.add.v4.f32 [%0], {%1, %2, %3, %4};"
            :: "l"(mp + i * 4),
               "f"(msg[4 * i + 0]), "f"(msg[4 * i + 1]),
               "f"(msg[4 * i + 2]), "f"(msg[4 * i + 3])
            : "memory");
    }
}

// ---------------------------------------------------------------------------
// Kernel 2: per-node GRU + output projection.
// ---------------------------------------------------------------------------
__device__ __forceinline__ float fast_sigmoid(float x) {
    return 1.0f / (1.0f + __expf(-x));
}
__device__ __forceinline__ float fast_tanh(float x) {
    float ax = fabsf(x);
    float e2 = __expf(-2.0f * ax);          // in (0,1], no overflow
    float th = (1.0f - e2) / (1.0f + e2);
    return copysignf(th, x);
}

__global__ void __launch_bounds__(256) node_kernel(
    const float* __restrict__ features,
    const float* __restrict__ W_ih,   // [48][16]
    const float* __restrict__ W_hh,   // [48][16]
    const float* __restrict__ b_ih,   // [48]
    const float* __restrict__ b_hh,   // [48]
    const float* __restrict__ W_out,  // [32][16]
    const float* __restrict__ b_out,  // [32]
    float* __restrict__ out,          // [N][32]
    int N)
{
    __shared__ float sWih[NGATE * HID];
    __shared__ float sWhh[NGATE * HID];
    __shared__ float sWo[COUT * HID];
    __shared__ float sbih[NGATE];
    __shared__ float sbhh[NGATE];
    __shared__ float sbo[COUT];

    for (int i = threadIdx.x; i < NGATE * HID; i += blockDim.x) {
        sWih[i] = W_ih[i];
        sWhh[i] = W_hh[i];
    }
    for (int i = threadIdx.x; i < COUT * HID; i += blockDim.x) sWo[i] = W_out[i];
    if (threadIdx.x < NGATE) {
        sbih[threadIdx.x] = b_ih[threadIdx.x];
        sbhh[threadIdx.x] = b_hh[threadIdx.x];
    }
    if (threadIdx.x < COUT) sbo[threadIdx.x] = b_out[threadIdx.x];
    __syncthreads();

    int n = blockIdx.x * blockDim.x + threadIdx.x;
    if (n >= N) return;

    float mv[HID], f[HID];
    {
        const float4* mp = reinterpret_cast<const float4*>(g_m + (size_t)n * HID);
        const float4* fp = reinterpret_cast<const float4*>(features + (size_t)n * HID);
#pragma unroll
        for (int i = 0; i < 4; i++) {
            float4 a = mp[i];
            mv[4*i+0] = a.x; mv[4*i+1] = a.y; mv[4*i+2] = a.z; mv[4*i+3] = a.w;
            float4 b = fp[i];
            f[4*i+0] = b.x; f[4*i+1] = b.y; f[4*i+2] = b.z; f[4*i+3] = b.w;
        }
    }

    // r gate
    float r[HID];
#pragma unroll
    for (int j = 0; j < HID; j++) {
        float a = sbih[j] + sbhh[j];
        const float* wi = sWih + j * HID;
        const float* wh = sWhh + j * HID;
#pragma unroll
        for (int k = 0; k < HID; k++) {
            a = fmaf(wi[k], mv[k], a);
            a = fmaf(wh[k], f[k], a);
        }
        r[j] = fast_sigmoid(a);
    }

    // z, n gates -> new hidden state
    float h[HID];
#pragma unroll
    for (int j = 0; j < HID; j++) {
        float az  = sbih[HID + j] + sbhh[HID + j];
        float ain = sbih[2 * HID + j];
        float ahn = sbhh[2 * HID + j];
        const float* wiz = sWih + (HID + j) * HID;
        const float* whz = sWhh + (HID + j) * HID;
        const float* win = sWih + (2 * HID + j) * HID;
        const float* whn = sWhh + (2 * HID + j) * HID;
#pragma unroll
        for (int k = 0; k < HID; k++) {
            az  = fmaf(wiz[k], mv[k], az);
            az  = fmaf(whz[k], f[k],  az);
            ain = fmaf(win[k], mv[k], ain);
            ahn = fmaf(whn[k], f[k],  ahn);
        }
        float z  = fast_sigmoid(az);
        float nn = fast_tanh(ain + r[j] * ahn);
        h[j] = (1.0f - z) * nn + z * f[j];
    }

    // output projection, store 4 at a time
    float4* op = reinterpret_cast<float4*>(out + (size_t)n * COUT);
#pragma unroll
    for (int c4 = 0; c4 < COUT / 4; c4++) {
        float4 o;
        float* ov = reinterpret_cast<float*>(&o);
#pragma unroll
        for (int q = 0; q < 4; q++) {
            int c = c4 * 4 + q;
            float a = sbo[c];
            const float* wo = sWo + c * HID;
#pragma unroll
            for (int k = 0; k < HID; k++) a = fmaf(wo[k], h[k], a);
            ov[q] = a;
        }
        op[c4] = o;
    }
}

// ---------------------------------------------------------------------------
// Launch
// ---------------------------------------------------------------------------
extern "C" void kernel_launch(void* const* d_in, const int* in_sizes, int n_in,
                              void* d_out, int out_size)
{
    const float* features   = (const float*)d_in[0];
    const int*   src        = (const int*)  d_in[1];
    const int*   dst        = (const int*)  d_in[2];
    const int*   etype      = (const int*)  d_in[3];
    const float* edge_table = (const float*)d_in[4];
    const float* W_ih       = (const float*)d_in[5];
    const float* W_hh       = (const float*)d_in[6];
    const float* b_ih       = (const float*)d_in[7];
    const float* b_hh       = (const float*)d_in[8];
    const float* W_out      = (const float*)d_in[9];
    const float* b_out      = (const float*)d_in[10];
    float*       out        = (float*)d_out;

    const int N = in_sizes[0] / HID;
    const int E = in_sizes[1];

    // 1) zero accumulator
    int n4 = (N * MSG) / 4;
    zero_m_kernel<<<(n4 + 255) / 256, 256>>>(n4);

    // 2) edge messages + scatter
    edge_kernel<<<(E + 255) / 256, 256>>>(features, src, dst, etype, edge_table, E);

    // 3) GRU + output projection
    node_kernel<<<(N + 255) / 256, 256>>>(features, W_ih, W_hh, b_ih, b_hh,
                                          W_out, b_out, out, N);
}

// round 6
// speedup vs baseline: 1.2934x; 1.2934x over previous
#include <cuda_runtime.h>
#include <cstdint>

// Problem constants (fixed shapes for this problem instance)
#define NMAX   100000
#define EMAX   1600000
#define HID    16
#define MSG    16
#define TTYPES 8
#define NGATE  48   // 3*HID
#define COUT   32

// Padded SMEM row stride for the edge-type table (helps the rare mixed-type
// boundary warps; type-uniform warps broadcast regardless).
#define ROWPAD 260

#define HIST_BLOCKS 256

// Scratch (device globals: no allocation allowed in kernel_launch).
__device__ __align__(16) float g_m[NMAX * MSG];        // segment-sum accumulator, 6.4 MB
__device__ __align__(16) int2  g_edge[EMAX];           // bucketed (src,dst), 12.8 MB
__device__ int g_blockhist[HIST_BLOCKS * TTYPES];
__device__ int g_off[TTYPES + 1];                      // bucket offsets
__device__ int g_cursor[TTYPES];                       // scatter cursors

// ---------------------------------------------------------------------------
// Kernel 1: zero g_m + per-block type histogram (no global atomics).
// ---------------------------------------------------------------------------
__global__ void __launch_bounds__(256) prep_kernel(
    const int* __restrict__ etype, int E, int n4)
{
    __shared__ int sh[TTYPES];
    if (threadIdx.x < TTYPES) sh[threadIdx.x] = 0;
    __syncthreads();

    int gid    = blockIdx.x * blockDim.x + threadIdx.x;
    int stride = gridDim.x * blockDim.x;

    // zero the accumulator (grid-stride, float4)
    float4* m4 = reinterpret_cast<float4*>(g_m);
    for (int i = gid; i < n4; i += stride)
        m4[i] = make_float4(0.f, 0.f, 0.f, 0.f);

    // histogram etype into SMEM
    for (int i = gid; i < E; i += stride)
        atomicAdd(&sh[etype[i]], 1);
    __syncthreads();

    if (threadIdx.x < TTYPES)
        g_blockhist[blockIdx.x * TTYPES + threadIdx.x] = sh[threadIdx.x];
}

// ---------------------------------------------------------------------------
// Kernel 2: tiny prefix-sum of the block histograms -> bucket offsets.
// ---------------------------------------------------------------------------
__global__ void prefix_kernel()
{
    __shared__ int tot[TTYPES];
    if (threadIdx.x < TTYPES) {
        int s = 0;
        for (int b = 0; b < HIST_BLOCKS; b++)
            s += g_blockhist[b * TTYPES + threadIdx.x];
        tot[threadIdx.x] = s;
    }
    __syncthreads();
    if (threadIdx.x == 0) {
        int run = 0;
        for (int t = 0; t < TTYPES; t++) {
            g_off[t]    = run;
            g_cursor[t] = run;
            run += tot[t];
        }
        g_off[TTYPES] = run;
    }
}

// ---------------------------------------------------------------------------
// Kernel 3: scatter edges into type buckets (block-aggregated cursors:
// only 8 global atomics per block).
// ---------------------------------------------------------------------------
__global__ void __launch_bounds__(256) scatter_kernel(
    const int* __restrict__ src,
    const int* __restrict__ dst,
    const int* __restrict__ etype,
    int E)
{
    __shared__ int scnt[TTYPES];
    __shared__ int sbase[TTYPES];
    if (threadIdx.x < TTYPES) scnt[threadIdx.x] = 0;
    __syncthreads();

    int e = blockIdx.x * blockDim.x + threadIdx.x;
    int t = 0, s = 0, d = 0, rank = 0;
    bool valid = (e < E);
    if (valid) {
        t = etype[e];
        s = src[e];
        d = dst[e];
        rank = atomicAdd(&scnt[t], 1);
    }
    __syncthreads();
    if (threadIdx.x < TTYPES)
        sbase[threadIdx.x] = atomicAdd(&g_cursor[threadIdx.x], scnt[threadIdx.x]);
    __syncthreads();
    if (valid)
        g_edge[sbase[t] + rank] = make_int2(s, d);
}

// ---------------------------------------------------------------------------
// Kernel 4: per-edge message + scatter-add over bucketed edges.
// Each thread handles 2 edges (warp covers 64 consecutive edges -> almost
// always type-uniform, so all A-row LDS are broadcasts shared by 2 edges).
// ---------------------------------------------------------------------------
__device__ __forceinline__ float dot16(const float4 a[4],
                                       const float4 h0, const float4 h1,
                                       const float4 h2, const float4 h3)
{
    float acc;
    acc = a[0].x * h0.x;             acc = fmaf(a[0].y, h0.y, acc);
    acc = fmaf(a[0].z, h0.z, acc);   acc = fmaf(a[0].w, h0.w, acc);
    acc = fmaf(a[1].x, h1.x, acc);   acc = fmaf(a[1].y, h1.y, acc);
    acc = fmaf(a[1].z, h1.z, acc);   acc = fmaf(a[1].w, h1.w, acc);
    acc = fmaf(a[2].x, h2.x, acc);   acc = fmaf(a[2].y, h2.y, acc);
    acc = fmaf(a[2].z, h2.z, acc);   acc = fmaf(a[2].w, h2.w, acc);
    acc = fmaf(a[3].x, h3.x, acc);   acc = fmaf(a[3].y, h3.y, acc);
    acc = fmaf(a[3].z, h3.z, acc);   acc = fmaf(a[3].w, h3.w, acc);
    return acc;
}

__global__ void __launch_bounds__(256) edge_kernel(
    const float* __restrict__ features,
    const float* __restrict__ edge_table,
    int E)
{
    __shared__ float sA[TTYPES * ROWPAD];
    __shared__ int   sOff[TTYPES + 1];

    for (int i = threadIdx.x; i < TTYPES * MSG * HID; i += blockDim.x) {
        int t = i >> 8;
        int k = i & 255;
        sA[t * ROWPAD + k] = edge_table[i];
    }
    if (threadIdx.x <= TTYPES) sOff[threadIdx.x] = g_off[threadIdx.x];
    __syncthreads();

    int warp = threadIdx.x >> 5;
    int lane = threadIdx.x & 31;
    int wbase = blockIdx.x * 512 + warp * 64;  // 64 edges per warp
    int e0 = wbase + lane;
    int e1 = wbase + 32 + lane;
    bool v0 = (e0 < E), v1 = (e1 < E);

    // Type from bucket boundaries (7 compares; warp-uniform except boundaries)
    int t0 = 0, t1 = 0;
#pragma unroll
    for (int t = 1; t < TTYPES; t++) {
        t0 += (e0 >= sOff[t]);
        t1 += (e1 >= sOff[t]);
    }

    int2 ed0 = v0 ? g_edge[e0] : make_int2(0, 0);
    int2 ed1 = v1 ? g_edge[e1] : make_int2(0, 0);

    const float4* hp0 = reinterpret_cast<const float4*>(features + (size_t)ed0.x * HID);
    const float4* hp1 = reinterpret_cast<const float4*>(features + (size_t)ed1.x * HID);
    float4 h00 = hp0[0], h01 = hp0[1], h02 = hp0[2], h03 = hp0[3];
    float4 h10 = hp1[0], h11 = hp1[1], h12 = hp1[2], h13 = hp1[3];

    const float* A0 = sA + t0 * ROWPAD;
    const float* A1 = sA + t1 * ROWPAD;
    bool same_t = (t0 == t1);

    float msg0[MSG], msg1[MSG];
#pragma unroll
    for (int r = 0; r < MSG; r++) {
        float4 a[4];
        const float4* ar = reinterpret_cast<const float4*>(A0 + r * HID);
        a[0] = ar[0]; a[1] = ar[1]; a[2] = ar[2]; a[3] = ar[3];
        msg0[r] = dot16(a, h00, h01, h02, h03);
        if (!same_t) {  // taken only in (rare) bucket-boundary warps
            const float4* br = reinterpret_cast<const float4*>(A1 + r * HID);
            a[0] = br[0]; a[1] = br[1]; a[2] = br[2]; a[3] = br[3];
        }
        msg1[r] = dot16(a, h10, h11, h12, h13);
    }

    // Vectorized L2 reductions: 4 x red.global.add.v4.f32 per edge.
    if (v0) {
        float* mp = g_m + (size_t)ed0.y * MSG;
#pragma unroll
        for (int i = 0; i < 4; i++) {
            asm volatile("red.global.add.v4.f32 [%0], {%1, %2, %3, %4};"
                :: "l"(mp + i * 4),
                   "f"(msg0[4*i+0]), "f"(msg0[4*i+1]),
                   "f"(msg0[4*i+2]), "f"(msg0[4*i+3]) : "memory");
        }
    }
    if (v1) {
        float* mp = g_m + (size_t)ed1.y * MSG;
#pragma unroll
        for (int i = 0; i < 4; i++) {
            asm volatile("red.global.add.v4.f32 [%0], {%1, %2, %3, %4};"
                :: "l"(mp + i * 4),
                   "f"(msg1[4*i+0]), "f"(msg1[4*i+1]),
                   "f"(msg1[4*i+2]), "f"(msg1[4*i+3]) : "memory");
        }
    }
}

// ---------------------------------------------------------------------------
// Kernel 5: per-node GRU + output projection.
// ---------------------------------------------------------------------------
__device__ __forceinline__ float fast_sigmoid(float x) {
    return 1.0f / (1.0f + __expf(-x));
}
__device__ __forceinline__ float fast_tanh(float x) {
    float ax = fabsf(x);
    float e2 = __expf(-2.0f * ax);
    float th = (1.0f - e2) / (1.0f + e2);
    return copysignf(th, x);
}

__global__ void __launch_bounds__(256) node_kernel(
    const float* __restrict__ features,
    const float* __restrict__ W_ih,   // [48][16]
    const float* __restrict__ W_hh,   // [48][16]
    const float* __restrict__ b_ih,   // [48]
    const float* __restrict__ b_hh,   // [48]
    const float* __restrict__ W_out,  // [32][16]
    const float* __restrict__ b_out,  // [32]
    float* __restrict__ out,          // [N][32]
    int N)
{
    __shared__ float sWih[NGATE * HID];
    __shared__ float sWhh[NGATE * HID];
    __shared__ float sWo[COUT * HID];
    __shared__ float sbih[NGATE];
    __shared__ float sbhh[NGATE];
    __shared__ float sbo[COUT];

    for (int i = threadIdx.x; i < NGATE * HID; i += blockDim.x) {
        sWih[i] = W_ih[i];
        sWhh[i] = W_hh[i];
    }
    for (int i = threadIdx.x; i < COUT * HID; i += blockDim.x) sWo[i] = W_out[i];
    if (threadIdx.x < NGATE) {
        sbih[threadIdx.x] = b_ih[threadIdx.x];
        sbhh[threadIdx.x] = b_hh[threadIdx.x];
    }
    if (threadIdx.x < COUT) sbo[threadIdx.x] = b_out[threadIdx.x];
    __syncthreads();

    int n = blockIdx.x * blockDim.x + threadIdx.x;
    if (n >= N) return;

    float mv[HID], f[HID];
    {
        const float4* mp = reinterpret_cast<const float4*>(g_m + (size_t)n * HID);
        const float4* fp = reinterpret_cast<const float4*>(features + (size_t)n * HID);
#pragma unroll
        for (int i = 0; i < 4; i++) {
            float4 a = mp[i];
            mv[4*i+0] = a.x; mv[4*i+1] = a.y; mv[4*i+2] = a.z; mv[4*i+3] = a.w;
            float4 b = fp[i];
            f[4*i+0] = b.x; f[4*i+1] = b.y; f[4*i+2] = b.z; f[4*i+3] = b.w;
        }
    }

    float r[HID];
#pragma unroll
    for (int j = 0; j < HID; j++) {
        float a = sbih[j] + sbhh[j];
        const float* wi = sWih + j * HID;
        const float* wh = sWhh + j * HID;
#pragma unroll
        for (int k = 0; k < HID; k++) {
            a = fmaf(wi[k], mv[k], a);
            a = fmaf(wh[k], f[k], a);
        }
        r[j] = fast_sigmoid(a);
    }

    float h[HID];
#pragma unroll
    for (int j = 0; j < HID; j++) {
        float az  = sbih[HID + j] + sbhh[HID + j];
        float ain = sbih[2 * HID + j];
        float ahn = sbhh[2 * HID + j];
        const float* wiz = sWih + (HID + j) * HID;
        const float* whz = sWhh + (HID + j) * HID;
        const float* win = sWih + (2 * HID + j) * HID;
        const float* whn = sWhh + (2 * HID + j) * HID;
#pragma unroll
        for (int k = 0; k < HID; k++) {
            az  = fmaf(wiz[k], mv[k], az);
            az  = fmaf(whz[k], f[k],  az);
            ain = fmaf(win[k], mv[k], ain);
            ahn = fmaf(whn[k], f[k],  ahn);
        }
        float z  = fast_sigmoid(az);
        float nn = fast_tanh(ain + r[j] * ahn);
        h[j] = (1.0f - z) * nn + z * f[j];
    }

    float4* op = reinterpret_cast<float4*>(out + (size_t)n * COUT);
#pragma unroll
    for (int c4 = 0; c4 < COUT / 4; c4++) {
        float4 o;
        float* ov = reinterpret_cast<float*>(&o);
#pragma unroll
        for (int q = 0; q < 4; q++) {
            int c = c4 * 4 + q;
            float a = sbo[c];
            const float* wo = sWo + c * HID;
#pragma unroll
            for (int k = 0; k < HID; k++) a = fmaf(wo[k], h[k], a);
            ov[q] = a;
        }
        op[c4] = o;
    }
}

// ---------------------------------------------------------------------------
// Launch
// ---------------------------------------------------------------------------
extern "C" void kernel_launch(void* const* d_in, const int* in_sizes, int n_in,
                              void* d_out, int out_size)
{
    const float* features   = (const float*)d_in[0];
    const int*   src        = (const int*)  d_in[1];
    const int*   dst        = (const int*)  d_in[2];
    const int*   etype      = (const int*)  d_in[3];
    const float* edge_table = (const float*)d_in[4];
    const float* W_ih       = (const float*)d_in[5];
    const float* W_hh       = (const float*)d_in[6];
    const float* b_ih       = (const float*)d_in[7];
    const float* b_hh       = (const float*)d_in[8];
    const float* W_out      = (const float*)d_in[9];
    const float* b_out      = (const float*)d_in[10];
    float*       out        = (float*)d_out;

    const int N = in_sizes[0] / HID;
    const int E = in_sizes[1];

    // 1) zero accumulator + per-block type histogram
    int n4 = (N * MSG) / 4;
    prep_kernel<<<HIST_BLOCKS, 256>>>(etype, E, n4);

    // 2) bucket offsets
    prefix_kernel<<<1, 256>>>();

    // 3) scatter edges into type buckets
    scatter_kernel<<<(E + 255) / 256, 256>>>(src, dst, etype, E);

    // 4) per-edge message + scatter-add (2 edges/thread, type-uniform warps)
    edge_kernel<<<(E + 511) / 512, 256>>>(features, edge_table, E);

    // 5) GRU + output projection
    node_kernel<<<(N + 255) / 256, 256>>>(features, W_ih, W_hh, b_ih, b_hh,
                                          W_out, b_out, out, N);
}

// round 7
// speedup vs baseline: 1.7255x; 1.3341x over previous
#include <cuda_runtime.h>
#include <cstdint>

// Problem constants (fixed shapes for this problem instance)
#define NMAX   100000
#define EMAX   1600000
#define HID    16
#define MSG    16
#define TTYPES 8
#define NGATE  48   // 3*HID
#define COUT   32

#define HIST_BLOCKS 256
#define EDGES_PER_WARP 256

// Scratch (device globals: no allocation allowed in kernel_launch).
__device__ __align__(16) float g_m[NMAX * MSG];        // segment-sum accumulator, 6.4 MB
__device__ __align__(16) int2  g_edge[EMAX];           // bucketed (src,dst), 12.8 MB
__device__ int g_blockhist[HIST_BLOCKS * TTYPES];
__device__ int g_off[TTYPES + 1];                      // bucket offsets
__device__ int g_cursor[TTYPES];                       // scatter cursors

// ---------------------------------------------------------------------------
// Kernel 1: zero g_m + per-block type histogram (no global atomics).
// ---------------------------------------------------------------------------
__global__ void __launch_bounds__(256) prep_kernel(
    const int* __restrict__ etype, int E, int n4)
{
    __shared__ int sh[TTYPES];
    if (threadIdx.x < TTYPES) sh[threadIdx.x] = 0;
    __syncthreads();

    int gid    = blockIdx.x * blockDim.x + threadIdx.x;
    int stride = gridDim.x * blockDim.x;

    float4* m4 = reinterpret_cast<float4*>(g_m);
    for (int i = gid; i < n4; i += stride)
        m4[i] = make_float4(0.f, 0.f, 0.f, 0.f);

    for (int i = gid; i < E; i += stride)
        atomicAdd(&sh[etype[i]], 1);
    __syncthreads();

    if (threadIdx.x < TTYPES)
        g_blockhist[blockIdx.x * TTYPES + threadIdx.x] = sh[threadIdx.x];
}

// ---------------------------------------------------------------------------
// Kernel 2: tiny prefix-sum of the block histograms -> bucket offsets.
// ---------------------------------------------------------------------------
__global__ void prefix_kernel()
{
    __shared__ int tot[TTYPES];
    if (threadIdx.x < TTYPES) {
        int s = 0;
        for (int b = 0; b < HIST_BLOCKS; b++)
            s += g_blockhist[b * TTYPES + threadIdx.x];
        tot[threadIdx.x] = s;
    }
    __syncthreads();
    if (threadIdx.x == 0) {
        int run = 0;
        for (int t = 0; t < TTYPES; t++) {
            g_off[t]    = run;
            g_cursor[t] = run;
            run += tot[t];
        }
        g_off[TTYPES] = run;
    }
}

// ---------------------------------------------------------------------------
// Kernel 3: scatter edges into type buckets (block-aggregated cursors).
// ---------------------------------------------------------------------------
__global__ void __launch_bounds__(256) scatter_kernel(
    const int* __restrict__ src,
    const int* __restrict__ dst,
    const int* __restrict__ etype,
    int E)
{
    __shared__ int scnt[TTYPES];
    __shared__ int sbase[TTYPES];
    if (threadIdx.x < TTYPES) scnt[threadIdx.x] = 0;
    __syncthreads();

    int e = blockIdx.x * blockDim.x + threadIdx.x;
    int t = 0, s = 0, d = 0, rank = 0;
    bool valid = (e < E);
    if (valid) {
        t = etype[e];
        s = src[e];
        d = dst[e];
        rank = atomicAdd(&scnt[t], 1);
    }
    __syncthreads();
    if (threadIdx.x < TTYPES)
        sbase[threadIdx.x] = atomicAdd(&g_cursor[threadIdx.x], scnt[threadIdx.x]);
    __syncthreads();
    if (valid)
        g_edge[sbase[t] + rank] = make_int2(s, d);
}

// ---------------------------------------------------------------------------
// Kernel 4: warp-cooperative edge messages + scatter-add.
// Warp owns a 256-edge tile of one type bucket (boundary tiles re-segment).
// Lane layout: edge-slot = lane>>2 (8 edges/iter), row-group = lane&3
// (4 msg rows per lane). A rows live in registers for the whole segment.
// ---------------------------------------------------------------------------
__device__ __forceinline__ float dotrow(const float4 a[4],
                                        const float4 h0, const float4 h1,
                                        const float4 h2, const float4 h3)
{
    float acc;
    acc = a[0].x * h0.x;             acc = fmaf(a[0].y, h0.y, acc);
    acc = fmaf(a[0].z, h0.z, acc);   acc = fmaf(a[0].w, h0.w, acc);
    acc = fmaf(a[1].x, h1.x, acc);   acc = fmaf(a[1].y, h1.y, acc);
    acc = fmaf(a[1].z, h1.z, acc);   acc = fmaf(a[1].w, h1.w, acc);
    acc = fmaf(a[2].x, h2.x, acc);   acc = fmaf(a[2].y, h2.y, acc);
    acc = fmaf(a[2].z, h2.z, acc);   acc = fmaf(a[2].w, h2.w, acc);
    acc = fmaf(a[3].x, h3.x, acc);   acc = fmaf(a[3].y, h3.y, acc);
    acc = fmaf(a[3].z, h3.z, acc);   acc = fmaf(a[3].w, h3.w, acc);
    return acc;
}

__global__ void __launch_bounds__(256, 2) edge_kernel(
    const float* __restrict__ features,
    const float* __restrict__ edge_table,
    int E)
{
    __shared__ int sOff[TTYPES + 1];
    if (threadIdx.x <= TTYPES) sOff[threadIdx.x] = g_off[threadIdx.x];
    __syncthreads();

    int gw   = blockIdx.x * 8 + (threadIdx.x >> 5);   // global warp id
    int lane = threadIdx.x & 31;
    int base = gw * EDGES_PER_WARP;
    if (base >= E) return;
    int end  = min(base + EDGES_PER_WARP, E);

    int egrp = lane >> 2;   // 0..7 edge slot within an iteration
    int rg   = lane & 3;    // 0..3 row group (rows 4*rg .. 4*rg+3)

    int cur = base;
    while (cur < end) {
        // type of current segment (warp-uniform)
        int t = 0;
#pragma unroll
        for (int i = 1; i < TTYPES; i++) t += (cur >= sOff[i]);
        int segEnd = min(end, sOff[t + 1]);

        // Load this lane's 4 A-rows (64 floats) into registers.
        // edge_table is 8 KB -> L2/L1-hot; loaded once per segment.
        float4 A0[4], A1[4], A2[4], A3[4];
        {
            const float4* At = reinterpret_cast<const float4*>(
                edge_table + t * (MSG * HID) + (rg * 4) * HID);
#pragma unroll
            for (int c = 0; c < 4; c++) {
                A0[c] = At[c];
                A1[c] = At[4 + c];
                A2[c] = At[8 + c];
                A3[c] = At[12 + c];
            }
        }

        for (int e8 = cur; e8 < segEnd; e8 += 8) {
            int e = e8 + egrp;
            bool v = (e < segEnd);
            int esafe = v ? e : (segEnd - 1);
            int2 ed = g_edge[esafe];                 // 4-lane dup -> L1 dedup

            const float4* hp = reinterpret_cast<const float4*>(
                features + (size_t)ed.x * HID);
            float4 h0 = hp[0], h1 = hp[1], h2 = hp[2], h3 = hp[3];

            float m0 = dotrow(A0, h0, h1, h2, h3);
            float m1 = dotrow(A1, h0, h1, h2, h3);
            float m2 = dotrow(A2, h0, h1, h2, h3);
            float m3 = dotrow(A3, h0, h1, h2, h3);

            if (v) {
                float* mp = g_m + (size_t)ed.y * MSG + rg * 4;
                asm volatile("red.global.add.v4.f32 [%0], {%1, %2, %3, %4};"
                    :: "l"(mp), "f"(m0), "f"(m1), "f"(m2), "f"(m3) : "memory");
            }
        }
        cur = segEnd;
    }
}

// ---------------------------------------------------------------------------
// Kernel 5: per-node GRU + output projection.
// ---------------------------------------------------------------------------
__device__ __forceinline__ float fast_sigmoid(float x) {
    return 1.0f / (1.0f + __expf(-x));
}
__device__ __forceinline__ float fast_tanh(float x) {
    float ax = fabsf(x);
    float e2 = __expf(-2.0f * ax);
    float th = (1.0f - e2) / (1.0f + e2);
    return copysignf(th, x);
}

__global__ void __launch_bounds__(256) node_kernel(
    const float* __restrict__ features,
    const float* __restrict__ W_ih,   // [48][16]
    const float* __restrict__ W_hh,   // [48][16]
    const float* __restrict__ b_ih,   // [48]
    const float* __restrict__ b_hh,   // [48]
    const float* __restrict__ W_out,  // [32][16]
    const float* __restrict__ b_out,  // [32]
    float* __restrict__ out,          // [N][32]
    int N)
{
    __shared__ float sWih[NGATE * HID];
    __shared__ float sWhh[NGATE * HID];
    __shared__ float sWo[COUT * HID];
    __shared__ float sbih[NGATE];
    __shared__ float sbhh[NGATE];
    __shared__ float sbo[COUT];

    for (int i = threadIdx.x; i < NGATE * HID; i += blockDim.x) {
        sWih[i] = W_ih[i];
        sWhh[i] = W_hh[i];
    }
    for (int i = threadIdx.x; i < COUT * HID; i += blockDim.x) sWo[i] = W_out[i];
    if (threadIdx.x < NGATE) {
        sbih[threadIdx.x] = b_ih[threadIdx.x];
        sbhh[threadIdx.x] = b_hh[threadIdx.x];
    }
    if (threadIdx.x < COUT) sbo[threadIdx.x] = b_out[threadIdx.x];
    __syncthreads();

    int n = blockIdx.x * blockDim.x + threadIdx.x;
    if (n >= N) return;

    float mv[HID], f[HID];
    {
        const float4* mp = reinterpret_cast<const float4*>(g_m + (size_t)n * HID);
        const float4* fp = reinterpret_cast<const float4*>(features + (size_t)n * HID);
#pragma unroll
        for (int i = 0; i < 4; i++) {
            float4 a = mp[i];
            mv[4*i+0] = a.x; mv[4*i+1] = a.y; mv[4*i+2] = a.z; mv[4*i+3] = a.w;
            float4 b = fp[i];
            f[4*i+0] = b.x; f[4*i+1] = b.y; f[4*i+2] = b.z; f[4*i+3] = b.w;
        }
    }

    float r[HID];
#pragma unroll
    for (int j = 0; j < HID; j++) {
        float a = sbih[j] + sbhh[j];
        const float* wi = sWih + j * HID;
        const float* wh = sWhh + j * HID;
#pragma unroll
        for (int k = 0; k < HID; k++) {
            a = fmaf(wi[k], mv[k], a);
            a = fmaf(wh[k], f[k], a);
        }
        r[j] = fast_sigmoid(a);
    }

    float h[HID];
#pragma unroll
    for (int j = 0; j < HID; j++) {
        float az  = sbih[HID + j] + sbhh[HID + j];
        float ain = sbih[2 * HID + j];
        float ahn = sbhh[2 * HID + j];
        const float* wiz = sWih + (HID + j) * HID;
        const float* whz = sWhh + (HID + j) * HID;
        const float* win = sWih + (2 * HID + j) * HID;
        const float* whn = sWhh + (2 * HID + j) * HID;
#pragma unroll
        for (int k = 0; k < HID; k++) {
            az  = fmaf(wiz[k], mv[k], az);
            az  = fmaf(whz[k], f[k],  az);
            ain = fmaf(win[k], mv[k], ain);
            ahn = fmaf(whn[k], f[k],  ahn);
        }
        float z  = fast_sigmoid(az);
        float nn = fast_tanh(ain + r[j] * ahn);
        h[j] = (1.0f - z) * nn + z * f[j];
    }

    float4* op = reinterpret_cast<float4*>(out + (size_t)n * COUT);
#pragma unroll
    for (int c4 = 0; c4 < COUT / 4; c4++) {
        float4 o;
        float* ov = reinterpret_cast<float*>(&o);
#pragma unroll
        for (int q = 0; q < 4; q++) {
            int c = c4 * 4 + q;
            float a = sbo[c];
            const float* wo = sWo + c * HID;
#pragma unroll
            for (int k = 0; k < HID; k++) a = fmaf(wo[k], h[k], a);
            ov[q] = a;
        }
        op[c4] = o;
    }
}

// ---------------------------------------------------------------------------
// Launch
// ---------------------------------------------------------------------------
extern "C" void kernel_launch(void* const* d_in, const int* in_sizes, int n_in,
                              void* d_out, int out_size)
{
    const float* features   = (const float*)d_in[0];
    const int*   src        = (const int*)  d_in[1];
    const int*   dst        = (const int*)  d_in[2];
    const int*   etype      = (const int*)  d_in[3];
    const float* edge_table = (const float*)d_in[4];
    const float* W_ih       = (const float*)d_in[5];
    const float* W_hh       = (const float*)d_in[6];
    const float* b_ih       = (const float*)d_in[7];
    const float* b_hh       = (const float*)d_in[8];
    const float* W_out      = (const float*)d_in[9];
    const float* b_out      = (const float*)d_in[10];
    float*       out        = (float*)d_out;

    const int N = in_sizes[0] / HID;
    const int E = in_sizes[1];

    // 1) zero accumulator + per-block type histogram
    int n4 = (N * MSG) / 4;
    prep_kernel<<<HIST_BLOCKS, 256>>>(etype, E, n4);

    // 2) bucket offsets
    prefix_kernel<<<1, 256>>>();

    // 3) scatter edges into type buckets
    scatter_kernel<<<(E + 255) / 256, 256>>>(src, dst, etype, E);

    // 4) warp-cooperative edge messages + scatter-add
    int tiles  = (E + EDGES_PER_WARP - 1) / EDGES_PER_WARP;
    int eblocks = (tiles + 7) / 8;
    edge_kernel<<<eblocks, 256>>>(features, edge_table, E);

    // 5) GRU + output projection
    node_kernel<<<(N + 255) / 256, 256>>>(features, W_ih, W_hh, b_ih, b_hh,
                                          W_out, b_out, out, N);
}